// round 13
// baseline (speedup 1.0000x reference)
#include <cuda_runtime.h>

// DropBlock, single fused kernel, 512-thread CTAs, V4=8 front-batched:
//   1. all 8 x float4 loads issued before any barrier (DRAM pipe full at t~0)
//   2. threads 0..55 load their own u row (14 float4) straight to registers,
//      bit-parallel row dilation -> column rolling OR -> popcount  [2 barriers]
//   3. scale = per-thread sum of 56 popcounts; mask*scale float4s to shared
//   4. consume the front-batched loads, multiply, streaming-store
// 512-thr CTAs give R12's prologue amortization (1568 instances) at R11's
// 64-reg / ~50% occupancy instead of R12's 80-reg / 31.5%.
// GAMMA = 0.1/49 * (56^2/50^2) = 0.00256 exactly.

#define H 56
#define W 56
#define HW 3136          // 56*56
#define HW4 784          // HW/4
#define GAMMA 0.00256f
#define THREADS 512
#define V4 8
#define V4_PER_CTA (THREADS * V4)   // 4096

__global__ void __launch_bounds__(THREADS) dropblock_fused(
    const float4* __restrict__ x, const float4* __restrict__ u4,
    float4* __restrict__ out) {
    __shared__ __align__(16) float4 sm4[HW4];    // mask*scale, 12.5 KB
    __shared__ unsigned long long rowd[H];
    __shared__ unsigned long long dil[H];
    __shared__ int pc[H];

    const int tid = threadIdx.x;
    const int base = blockIdx.x * V4_PER_CTA + tid;

    // ── 1. front-batch ALL 8 stream loads (before any barrier) ──
    float4 v[V4];
    #pragma unroll
    for (int k = 0; k < V4; ++k)
        v[k] = __ldcs(&x[base + k * THREADS]);

    // ── 2. row phase: threads 0..55 load own u row to regs, dilate ──
    if (tid < H) {
        float4 r[14];
        #pragma unroll
        for (int j = 0; j < 14; ++j) r[j] = __ldg(&u4[tid * 14 + j]);
        unsigned long long s = 0ULL;
        #pragma unroll
        for (int j = 0; j < 14; ++j) {
            const int w = j * 4;
            s |= (unsigned long long)(r[j].x < GAMMA) << (w + 0);
            s |= (unsigned long long)(r[j].y < GAMMA) << (w + 1);
            s |= (unsigned long long)(r[j].z < GAMMA) << (w + 2);
            s |= (unsigned long long)(r[j].w < GAMMA) << (w + 3);
        }
        unsigned long long a = s | (s << 1);     // shifts {0,1}
        unsigned long long b = a | (a << 2);     // shifts {0..3}
        unsigned long long c = b | (b << 3);     // shifts {0..6}
        rowd[tid] = c & ((1ULL << W) - 1ULL);
    }
    __syncthreads();

    // ── 3. column phase: rolling OR over rows h-6..h + popcount ──
    if (tid < H) {
        const int h0 = tid - 6 < 0 ? 0 : tid - 6;
        unsigned long long d = 0ULL;
        for (int h = h0; h <= tid; ++h) d |= rowd[h];
        dil[tid] = d;
        pc[tid] = __popcll(d);
    }
    __syncthreads();

    // ── 4. scale (redundant per-thread sum) + mask float4s to shared ──
    int tot = 0;
    #pragma unroll
    for (int h = 0; h < H; ++h) tot += pc[h];
    const float scale = (float)HW / (float)(HW - tot);
    #pragma unroll
    for (int j = 0; j < 2; ++j) {
        const int s4 = tid + j * THREADS;
        if (s4 < HW4) {
            const int h = s4 / 14;               // 14 float4 per row
            const int w0 = (s4 % 14) * 4;
            const unsigned long long bits = dil[h] >> w0;
            float4 mk;
            mk.x = (bits & 1ULL) ? 0.0f : scale;
            mk.y = (bits & 2ULL) ? 0.0f : scale;
            mk.z = (bits & 4ULL) ? 0.0f : scale;
            mk.w = (bits & 8ULL) ? 0.0f : scale;
            sm4[s4] = mk;
        }
    }
    __syncthreads();

    // ── 5. consume front-batched loads, multiply, streaming-store ──
    int s4 = base % HW4;                         // incremental wrap
    #pragma unroll
    for (int k = 0; k < V4; ++k) {
        const float4 mk = sm4[s4];
        v[k].x *= mk.x; v[k].y *= mk.y; v[k].z *= mk.z; v[k].w *= mk.w;
        __stcs(&out[base + k * THREADS], v[k]);
        s4 += THREADS;
        if (s4 >= HW4) s4 -= HW4;
    }
}

extern "C" void kernel_launch(void* const* d_in, const int* in_sizes, int n_in,
                              void* d_out, int out_size) {
    const float* x = (const float*)d_in[0];   // (32,256,56,56) f32
    const float* u = (const float*)d_in[1];   // (56,56) f32

    // 6,422,528 float4 = 1568 CTAs * 512 thr * 8
    const int n4 = out_size / 4;
    dropblock_fused<<<n4 / V4_PER_CTA, THREADS>>>(
        (const float4*)x, (const float4*)u, (float4*)d_out);
}

// round 14
// speedup vs baseline: 1.1174x; 1.1174x over previous
#include <cuda_runtime.h>

// DropBlock, single fused kernel (R11 geometry + slim prologue):
//   1. front-batch all 8 x float4 loads (before any barrier)
//   2. threads 0..55 load their own u row (14 float4) straight to registers,
//      bit-parallel row dilation  [no shared staging of u]
//   3. column rolling OR + popcount; threads 0..63 (two FULL warps,
//      lanes 56-63 contribute 0) shuffle-reduce the total -> 2 partials
//   4. scale = HW/(HW - partial0 - partial1)  (2 LDS + adds per thread,
//      replaces 56 LDS + 56 IADD per thread of R11)
//   5. mask*scale float4s to shared; consume loads; streaming-store
// GAMMA = 0.1/49 * (56^2/50^2) = 0.00256 exactly.

#define H 56
#define W 56
#define HW 3136          // 56*56
#define HW4 784          // HW/4
#define GAMMA 0.00256f
#define THREADS 256
#define V4 8
#define V4_PER_CTA (THREADS * V4)   // 2048

__global__ void __launch_bounds__(THREADS) dropblock_fused(
    const float4* __restrict__ x, const float4* __restrict__ u4,
    float4* __restrict__ out) {
    __shared__ __align__(16) float4 sm4[HW4];    // mask*scale, 12.5 KB
    __shared__ unsigned long long rowd[H];
    __shared__ unsigned long long dil[H];
    __shared__ int partial[2];

    const int tid = threadIdx.x;
    const int base = blockIdx.x * V4_PER_CTA + tid;

    // ── 1. front-batch ALL 8 stream loads (before any barrier) ──
    float4 v[V4];
    #pragma unroll
    for (int k = 0; k < V4; ++k)
        v[k] = __ldcs(&x[base + k * THREADS]);

    // ── 2. row phase: threads 0..55 load own u row to regs, dilate ──
    if (tid < H) {
        float4 r[14];
        #pragma unroll
        for (int j = 0; j < 14; ++j) r[j] = __ldg(&u4[tid * 14 + j]);
        unsigned long long s = 0ULL;
        #pragma unroll
        for (int j = 0; j < 14; ++j) {
            const int w = j * 4;
            s |= (unsigned long long)(r[j].x < GAMMA) << (w + 0);
            s |= (unsigned long long)(r[j].y < GAMMA) << (w + 1);
            s |= (unsigned long long)(r[j].z < GAMMA) << (w + 2);
            s |= (unsigned long long)(r[j].w < GAMMA) << (w + 3);
        }
        unsigned long long a = s | (s << 1);     // shifts {0,1}
        unsigned long long b = a | (a << 2);     // shifts {0..3}
        unsigned long long c = b | (b << 3);     // shifts {0..6}
        rowd[tid] = c & ((1ULL << W) - 1ULL);
    }
    __syncthreads();

    // ── 3. column phase + warp-reduced popcount sum (two FULL warps) ──
    if (tid < 64) {
        int p = 0;
        if (tid < H) {
            const int h0 = tid - 6 < 0 ? 0 : tid - 6;
            unsigned long long d = 0ULL;
            for (int h = h0; h <= tid; ++h) d |= rowd[h];
            dil[tid] = d;
            p = __popcll(d);
        }
        // full-warp shuffle reduce (lanes 56-63 carry 0; no divergence)
        #pragma unroll
        for (int off = 16; off > 0; off >>= 1)
            p += __shfl_down_sync(0xFFFFFFFFu, p, off);
        if ((tid & 31) == 0) partial[tid >> 5] = p;
    }
    __syncthreads();

    // ── 4+5. scale, mask float4s to shared ──
    const float scale = (float)HW / (float)(HW - partial[0] - partial[1]);
    #pragma unroll
    for (int j = 0; j < 4; ++j) {
        const int s4 = tid + j * THREADS;
        if (s4 < HW4) {
            const int h = s4 / 14;               // 14 float4 per row
            const int w0 = (s4 % 14) * 4;
            const unsigned long long bits = dil[h] >> w0;
            float4 mk;
            mk.x = (bits & 1ULL) ? 0.0f : scale;
            mk.y = (bits & 2ULL) ? 0.0f : scale;
            mk.z = (bits & 4ULL) ? 0.0f : scale;
            mk.w = (bits & 8ULL) ? 0.0f : scale;
            sm4[s4] = mk;
        }
    }
    __syncthreads();

    // ── 6. consume front-batched loads, multiply, streaming-store ──
    int s4 = base % HW4;                         // incremental wrap
    #pragma unroll
    for (int k = 0; k < V4; ++k) {
        const float4 mk = sm4[s4];
        v[k].x *= mk.x; v[k].y *= mk.y; v[k].z *= mk.z; v[k].w *= mk.w;
        __stcs(&out[base + k * THREADS], v[k]);
        s4 += THREADS;
        if (s4 >= HW4) s4 -= HW4;
    }
}

extern "C" void kernel_launch(void* const* d_in, const int* in_sizes, int n_in,
                              void* d_out, int out_size) {
    const float* x = (const float*)d_in[0];   // (32,256,56,56) f32
    const float* u = (const float*)d_in[1];   // (56,56) f32

    // 6,422,528 float4 = 3136 CTAs * 256 thr * 8
    const int n4 = out_size / 4;
    dropblock_fused<<<n4 / V4_PER_CTA, THREADS>>>(
        (const float4*)x, (const float4*)u, (float4*)d_out);
}

// round 15
// speedup vs baseline: 1.1758x; 1.0523x over previous
#include <cuda_runtime.h>

// DropBlock, single fused kernel = R11 + shuffle-reduced scale sum ONLY.
//   1. front-batch all 8 x float4 loads (before any barrier)
//   2. stage u to shared (coalesced, no big register arrays -> 64 regs)
//   3. bit-parallel row dilation; column rolling OR + popcount
//   4. scale sum: two FULL warps shuffle-reduce the 56 popcounts -> 2
//      partials (replaces R11's 56 LDS + 56 IADD in ALL 256 threads,
//      ~28K instr/CTA, the single biggest ALU item at 20.5% pipe)
//   5. mask*scale float4s to shared; consume loads; streaming-store
// R13/R14 lesson: direct per-thread row loads (r[14]) cost +2 regs and a
// CTA/SM slot -> occupancy cliff. Shared staging stays.
// GAMMA = 0.1/49 * (56^2/50^2) = 0.00256 exactly.

#define H 56
#define W 56
#define HW 3136          // 56*56
#define HW4 784          // HW/4
#define GAMMA 0.00256f
#define THREADS 256
#define V4 8
#define V4_PER_CTA (THREADS * V4)   // 2048

__global__ void __launch_bounds__(THREADS) dropblock_fused(
    const float4* __restrict__ x, const float4* __restrict__ u4,
    float4* __restrict__ out) {
    // 12.5KB buffer reused: u floats (prologue) then mask float4s (epilogue)
    __shared__ __align__(16) float s_buf[HW];
    __shared__ unsigned long long rowd[H];
    __shared__ unsigned long long dil[H];
    __shared__ int partial[2];

    const int tid = threadIdx.x;
    const int base = blockIdx.x * V4_PER_CTA + tid;

    // ── 1. front-batch ALL 8 stream loads (before any barrier) ──
    float4 v[V4];
    #pragma unroll
    for (int k = 0; k < V4; ++k)
        v[k] = __ldcs(&x[base + k * THREADS]);

    // ── 2. stage u into shared (784 float4 over 256 threads, coalesced) ──
    float4* s_buf4 = reinterpret_cast<float4*>(s_buf);
    #pragma unroll
    for (int j = 0; j < 4; ++j) {
        const int i = tid + j * THREADS;
        if (i < HW4) s_buf4[i] = __ldg(&u4[i]);
    }
    __syncthreads();

    // ── 3. row-wise backward dilation (width 7) as bit ops ──
    if (tid < H) {
        unsigned long long s = 0ULL;
        #pragma unroll
        for (int w = 0; w < W; ++w)
            s |= (unsigned long long)(s_buf[tid * W + w] < GAMMA) << w;
        unsigned long long a = s | (s << 1);     // shifts {0,1}
        unsigned long long b = a | (a << 2);     // shifts {0..3}
        unsigned long long c = b | (b << 3);     // shifts {0..6}
        rowd[tid] = c & ((1ULL << W) - 1ULL);
    }
    __syncthreads();

    // ── 4. column phase + shuffle-reduced popcount sum (two FULL warps) ──
    if (tid < 64) {
        int p = 0;
        if (tid < H) {
            const int h0 = tid - 6 < 0 ? 0 : tid - 6;
            unsigned long long d = 0ULL;
            for (int h = h0; h <= tid; ++h) d |= rowd[h];
            dil[tid] = d;
            p = __popcll(d);
        }
        // full-warp shuffle reduce (lanes 56-63 carry 0; no divergence)
        #pragma unroll
        for (int off = 16; off > 0; off >>= 1)
            p += __shfl_down_sync(0xFFFFFFFFu, p, off);
        if ((tid & 31) == 0) partial[tid >> 5] = p;
    }
    __syncthreads();

    // ── 5. scale (2 LDS + 2 adds) + mask float4s over dead u buffer ──
    const float scale = (float)HW / (float)(HW - partial[0] - partial[1]);
    #pragma unroll
    for (int j = 0; j < 4; ++j) {
        const int s4 = tid + j * THREADS;
        if (s4 < HW4) {
            const int h = s4 / 14;               // 14 float4 per row
            const int w0 = (s4 % 14) * 4;
            const unsigned long long bits = dil[h] >> w0;
            float4 mk;
            mk.x = (bits & 1ULL) ? 0.0f : scale;
            mk.y = (bits & 2ULL) ? 0.0f : scale;
            mk.z = (bits & 4ULL) ? 0.0f : scale;
            mk.w = (bits & 8ULL) ? 0.0f : scale;
            s_buf4[s4] = mk;
        }
    }
    __syncthreads();

    // ── 6. consume the front-batched loads, multiply, streaming-store ──
    int s4 = base % HW4;                         // incremental wrap
    #pragma unroll
    for (int k = 0; k < V4; ++k) {
        const float4 mk = s_buf4[s4];
        v[k].x *= mk.x; v[k].y *= mk.y; v[k].z *= mk.z; v[k].w *= mk.w;
        __stcs(&out[base + k * THREADS], v[k]);
        s4 += THREADS;
        if (s4 >= HW4) s4 -= HW4;
    }
}

extern "C" void kernel_launch(void* const* d_in, const int* in_sizes, int n_in,
                              void* d_out, int out_size) {
    const float* x = (const float*)d_in[0];   // (32,256,56,56) f32
    const float* u = (const float*)d_in[1];   // (56,56) f32

    // 6,422,528 float4 = 3136 CTAs * 256 thr * 8
    const int n4 = out_size / 4;
    dropblock_fused<<<n4 / V4_PER_CTA, THREADS>>>(
        (const float4*)x, (const float4*)u, (float4*)d_out);
}